// round 4
// baseline (speedup 1.0000x reference)
#include <cuda_runtime.h>
#include <math.h>

#define BATCH 8192
#define DIN   3200
#define DH    128
#define NEXP  5

// ---------------- scratch (static device memory; no allocation) ----------------
__device__ float g_pool[BATCH * 16 * 12 * 12];   // conv1+pool output  [B,16,12,12]
__device__ float g_feat[BATCH * DIN];            // conv2 output       [B,3200]
__device__ float g_gw  [BATCH * NEXP];           // routing weights    [B,5]
__device__ float g_e1  [BATCH * NEXP * DH];      // expert layer-1     [B,5*128]

// ================= Kernel 1: conv1 (5x5 VALID) + ReLU + maxpool 2x2 =============
// grid = BATCH, block = 144 (one thread per pooled 12x12 position, loops channels)
__global__ void k_conv1pool(const float* __restrict__ x,
                            const float* __restrict__ w,
                            const float* __restrict__ bias,
                            float* __restrict__ out) {
    __shared__ float s_img[784];
    __shared__ float s_w[400];
    __shared__ float s_b[16];
    int b = blockIdx.x;
    int tid = threadIdx.x;
    const float* xin = x + b * 784;
    for (int i = tid; i < 784; i += 144) s_img[i] = xin[i];
    for (int i = tid; i < 400; i += 144) s_w[i] = w[i];
    if (tid < 16) s_b[tid] = bias[tid];
    __syncthreads();

    int py = tid / 12, px = tid % 12;
    // 6x6 input patch covering the 2x2 window of 5x5 convs
    float xr[6][6];
#pragma unroll
    for (int r = 0; r < 6; r++)
#pragma unroll
        for (int c = 0; c < 6; c++)
            xr[r][c] = s_img[(2 * py + r) * 28 + 2 * px + c];

    float* o = out + (b * 16) * 144 + py * 12 + px;
#pragma unroll
    for (int ch = 0; ch < 16; ch++) {
        float bb = s_b[ch];
        float a00 = bb, a01 = bb, a10 = bb, a11 = bb;
        const float* wc = &s_w[ch * 25];
#pragma unroll
        for (int ky = 0; ky < 5; ky++)
#pragma unroll
            for (int kx = 0; kx < 5; kx++) {
                float wv = wc[ky * 5 + kx];
                a00 += wv * xr[ky][kx];
                a01 += wv * xr[ky][kx + 1];
                a10 += wv * xr[ky + 1][kx];
                a11 += wv * xr[ky + 1][kx + 1];
            }
        float m = fmaxf(fmaxf(a00, a01), fmaxf(a10, a11));
        o[ch * 144] = fmaxf(m, 0.0f);   // max of relus == relu of max
    }
}

// ================= Kernel 2: conv2 (3x3 VALID over 16ch) + ReLU -> feat =========
// grid = BATCH, block = 160. Microtile: 4 output channels x 5 positions per thread.
__global__ void k_conv2(const float* __restrict__ pool,
                        const float* __restrict__ w,
                        const float* __restrict__ bias,
                        float* __restrict__ feat) {
    __shared__ float s_in[2304];    // [16][12][12]
    __shared__ float s_w[4608];     // [32][16][3][3]
    __shared__ float s_b[32];
    int b = blockIdx.x;
    int tid = threadIdx.x;
    const float* pin = pool + b * 2304;
    for (int i = tid; i < 2304; i += 160) s_in[i] = pin[i];
    for (int i = tid; i < 4608; i += 160) s_w[i] = w[i];
    if (tid < 32) s_b[tid] = bias[tid];
    __syncthreads();

    int ot = tid / 20;            // 0..7 -> channel base ot*4
    int pt = tid % 20;            // 0..19 -> oy = pt/2, ox base = (pt%2)*5
    int ob = ot * 4;
    int oy = pt >> 1;
    int oxb = (pt & 1) * 5;

    float acc[4][5];
#pragma unroll
    for (int a = 0; a < 4; a++) {
        float bb = s_b[ob + a];
#pragma unroll
        for (int j = 0; j < 5; j++) acc[a][j] = bb;
    }

    for (int i = 0; i < 16; i++) {
#pragma unroll
        for (int ky = 0; ky < 3; ky++) {
            const float* ir = &s_in[(i * 12 + oy + ky) * 12 + oxb];
            float inr[7];
#pragma unroll
            for (int t = 0; t < 7; t++) inr[t] = ir[t];
#pragma unroll
            for (int kx = 0; kx < 3; kx++) {
                float wv[4];
#pragma unroll
                for (int a = 0; a < 4; a++)
                    wv[a] = s_w[((ob + a) * 16 + i) * 9 + ky * 3 + kx];
#pragma unroll
                for (int a = 0; a < 4; a++)
#pragma unroll
                    for (int j = 0; j < 5; j++)
                        acc[a][j] += wv[a] * inr[kx + j];
            }
        }
    }

    float* frow = feat + b * DIN;
#pragma unroll
    for (int a = 0; a < 4; a++)
#pragma unroll
        for (int j = 0; j < 5; j++)
            frow[(ob + a) * 100 + oy * 10 + oxb + j] = fmaxf(acc[a][j], 0.0f);
}

// ================= Kernel 3: GLU router + top-3 + softmax -> weights ============
// one warp per batch row; block 256 (8 rows), grid 1024
__global__ void k_router(const float* __restrict__ feat,
                         const float* __restrict__ Wg,  const float* __restrict__ bg,
                         const float* __restrict__ Wgl, const float* __restrict__ bgl,
                         float* __restrict__ gw) {
    int warp = (blockIdx.x * blockDim.x + threadIdx.x) >> 5;
    int lane = threadIdx.x & 31;
    if (warp >= BATCH) return;
    const float* f = feat + warp * DIN;
    float acc[10];
#pragma unroll
    for (int e = 0; e < 10; e++) acc[e] = 0.0f;
    for (int k = lane; k < DIN; k += 32) {
        float fv = f[k];
        const float* wg = Wg  + k * NEXP;
        const float* wl = Wgl + k * NEXP;
#pragma unroll
        for (int e = 0; e < NEXP; e++) {
            acc[e]        += fv * __ldg(&wg[e]);
            acc[5 + e]    += fv * __ldg(&wl[e]);
        }
    }
#pragma unroll
    for (int off = 16; off; off >>= 1)
#pragma unroll
        for (int e = 0; e < 10; e++)
            acc[e] += __shfl_down_sync(0xFFFFFFFFu, acc[e], off);

    if (lane == 0) {
        float gate[NEXP];
#pragma unroll
        for (int e = 0; e < NEXP; e++) {
            float g = acc[e] + bg[e];
            float s = 1.0f / (1.0f + expf(-(acc[5 + e] + bgl[e])));
            gate[e] = g * s;
        }
        // top-3 (strict > keeps first-occurrence order like lax.top_k)
        float v0 = -1e30f, v1 = -1e30f, v2 = -1e30f;
        int i0 = 0, i1 = 0, i2 = 0;
#pragma unroll
        for (int e = 0; e < NEXP; e++) {
            float g = gate[e];
            if (g > v0)      { v2 = v1; i2 = i1; v1 = v0; i1 = i0; v0 = g; i0 = e; }
            else if (g > v1) { v2 = v1; i2 = i1; v1 = g;  i1 = e; }
            else if (g > v2) { v2 = g;  i2 = e; }
        }
        float e0 = 1.0f;                // expf(v0 - v0)
        float e1 = expf(v1 - v0);
        float e2 = expf(v2 - v0);
        float inv = 1.0f / (e0 + e1 + e2);
        float wout[NEXP];
#pragma unroll
        for (int e = 0; e < NEXP; e++) wout[e] = 0.0f;
        wout[i0] = e0 * inv; wout[i1] = e1 * inv; wout[i2] = e2 * inv;
#pragma unroll
        for (int e = 0; e < NEXP; e++) gw[warp * NEXP + e] = wout[e];
    }
}

// ================= Kernel 4: e1 = tanh(feat @ W1e + b1e)  (the big GEMM) ========
// C[8192,640], tile 128x128 (blockIdx.y = expert), BK=32, 256 threads, 8x8 microtile
#define BK 32
__global__ void k_gemm1(const float* __restrict__ A,     // [8192,3200]
                        const float* __restrict__ W1e,   // [5,3200,128]
                        const float* __restrict__ b1e,   // [5,128]
                        float* __restrict__ E1) {        // [8192,640]
    __shared__ float As[BK][129];   // transposed, padded (conflict-free scatter)
    __shared__ float Bs[BK][128];
    int mb = blockIdx.x;            // 0..63
    int e  = blockIdx.y;            // 0..4
    int tid = threadIdx.x;
    const float* Ablk = A + (size_t)mb * 128 * DIN;
    const float* Bblk = W1e + (size_t)e * DIN * DH;

    float acc[8][8];
#pragma unroll
    for (int i = 0; i < 8; i++)
#pragma unroll
        for (int j = 0; j < 8; j++) acc[i][j] = 0.0f;

    int tm = (tid / 16) * 8;
    int tn = (tid % 16) * 8;

    for (int k0 = 0; k0 < DIN; k0 += BK) {
        // A tile: 128 rows x 32 k, transpose into As[k][m]
#pragma unroll
        for (int l = 0; l < 4; l++) {
            int f = tid + l * 256;         // 0..1023
            int row = f >> 3;
            int c4  = (f & 7) << 2;
            float4 v = *(const float4*)&Ablk[(size_t)row * DIN + k0 + c4];
            As[c4 + 0][row] = v.x;
            As[c4 + 1][row] = v.y;
            As[c4 + 2][row] = v.z;
            As[c4 + 3][row] = v.w;
        }
        // B tile: 32 k-rows x 128 cols direct
#pragma unroll
        for (int l = 0; l < 4; l++) {
            int f = tid + l * 256;
            int row = f >> 5;
            int c4  = (f & 31) << 2;
            *(float4*)&Bs[row][c4] = *(const float4*)&Bblk[(size_t)(k0 + row) * DH + c4];
        }
        __syncthreads();
#pragma unroll
        for (int k = 0; k < BK; k++) {
            float a[8], bb[8];
#pragma unroll
            for (int i = 0; i < 8; i++) a[i] = As[k][tm + i];
            *(float4*)&bb[0] = *(float4*)&Bs[k][tn];
            *(float4*)&bb[4] = *(float4*)&Bs[k][tn + 4];
#pragma unroll
            for (int i = 0; i < 8; i++)
#pragma unroll
                for (int j = 0; j < 8; j++)
                    acc[i][j] += a[i] * bb[j];
        }
        __syncthreads();
    }

    const float* bias = b1e + e * DH;
    float bj[8];
#pragma unroll
    for (int j = 0; j < 8; j++) bj[j] = bias[tn + j];
#pragma unroll
    for (int i = 0; i < 8; i++) {
        int m = mb * 128 + tm + i;
        float* orow = E1 + (size_t)m * (NEXP * DH) + e * DH + tn;
#pragma unroll
        for (int j = 0; j < 8; j++)
            orow[j] = tanhf(acc[i][j] + bj[j]);
    }
}

// ====== Kernel 5: e2 = tanh(e1 @ W2e + b2e); moe = sum_e w_e*e2; head; softmax ==
// block handles 32 batch rows, 256 threads (thread = column h, 16 rows)
__global__ void k_expert2(const float* __restrict__ E1,    // [8192,640]
                          const float* __restrict__ W2e,   // [5,128,128]
                          const float* __restrict__ b2e,   // [5,128]
                          const float* __restrict__ gw,    // [8192,5]
                          const float* __restrict__ Ws,    // [128,10]
                          const float* __restrict__ bs,    // [10]
                          float* __restrict__ out) {       // [8192,10]
    __shared__ float s_e1[32][128];
    __shared__ float s_w2[32][128];   // w2 chunk; reused as s_moe at the end
    __shared__ float s_gw[32][5];
    __shared__ float s_ws[1280];
    __shared__ float s_log[32][10];

    int b0 = blockIdx.x * 32;
    int tid = threadIdx.x;
    int h  = tid & 127;
    int rb = (tid >> 7) * 16;         // row base: 0 or 16

    for (int i = tid; i < 160; i += 256)
        s_gw[i / 5][i % 5] = gw[(b0 + i / 5) * NEXP + (i % 5)];
    for (int i = tid; i < 1280; i += 256) s_ws[i] = Ws[i];

    float moe[16];
#pragma unroll
    for (int r = 0; r < 16; r++) moe[r] = 0.0f;

    for (int e = 0; e < NEXP; e++) {
        __syncthreads();   // previous expert's compute done before overwriting s_e1
        for (int i = tid; i < 4096; i += 256) {
            int r = i >> 7, hh = i & 127;
            s_e1[r][hh] = E1[(size_t)(b0 + r) * (NEXP * DH) + e * DH + hh];
        }
        float pre[16];
        float bias = b2e[e * DH + h];
#pragma unroll
        for (int r = 0; r < 16; r++) pre[r] = bias;

        for (int hc = 0; hc < 4; hc++) {
            __syncthreads();   // prev chunk consumed (and e1 ready on hc==0)
            for (int i = tid; i < 4096; i += 256) {
                int hi = i >> 7, hh = i & 127;
                s_w2[hi][hh] = W2e[(size_t)e * DH * DH + (hc * 32 + hi) * DH + hh];
            }
            __syncthreads();
#pragma unroll 8
            for (int hi = 0; hi < 32; hi++) {
                float wv = s_w2[hi][h];
#pragma unroll
                for (int r = 0; r < 16; r++)
                    pre[r] += s_e1[rb + r][hc * 32 + hi] * wv;
            }
        }
        float we[16];
#pragma unroll
        for (int r = 0; r < 16; r++) we[r] = s_gw[rb + r][e];
#pragma unroll
        for (int r = 0; r < 16; r++)
            moe[r] += we[r] * tanhf(pre[r]);
    }

    // head: logits = moe @ Ws + bs, then softmax per row
    __syncthreads();
#pragma unroll
    for (int r = 0; r < 16; r++) s_w2[rb + r][h] = moe[r];   // s_w2 reused as moe
    __syncthreads();

    // 320 work items (32 rows x 10 classes) over 256 threads — MUST grid-stride
    for (int i = tid; i < 320; i += 256) {
        int r = i / 10, c = i % 10;
        float a = bs[c];
#pragma unroll 16
        for (int hh = 0; hh < 128; hh++)
            a += s_w2[r][hh] * s_ws[hh * 10 + c];
        s_log[r][c] = a;
    }
    __syncthreads();
    if (tid < 32) {
        int r = tid;
        float m = -1e30f;
#pragma unroll
        for (int c = 0; c < 10; c++) m = fmaxf(m, s_log[r][c]);
        float ex[10], s = 0.0f;
#pragma unroll
        for (int c = 0; c < 10; c++) { ex[c] = expf(s_log[r][c] - m); s += ex[c]; }
        float inv = 1.0f / s;
        float* orow = out + (size_t)(b0 + r) * 10;
#pragma unroll
        for (int c = 0; c < 10; c++) orow[c] = ex[c] * inv;
    }
}

// =============================== launcher =======================================
extern "C" void kernel_launch(void* const* d_in, const int* in_sizes, int n_in,
                              void* d_out, int out_size) {
    const float* x       = (const float*)d_in[0];
    const float* conv1_w = (const float*)d_in[1];
    const float* conv1_b = (const float*)d_in[2];
    const float* conv2_w = (const float*)d_in[3];
    const float* conv2_b = (const float*)d_in[4];
    const float* Wg      = (const float*)d_in[5];
    const float* bg      = (const float*)d_in[6];
    const float* Wglu    = (const float*)d_in[7];
    const float* bglu    = (const float*)d_in[8];
    const float* W1e     = (const float*)d_in[9];
    const float* b1e     = (const float*)d_in[10];
    const float* W2e     = (const float*)d_in[11];
    const float* b2e     = (const float*)d_in[12];
    const float* Ws      = (const float*)d_in[13];
    const float* bs      = (const float*)d_in[14];
    float* out = (float*)d_out;

    float *pool, *feat, *gwp, *e1;
    cudaGetSymbolAddress((void**)&pool, g_pool);
    cudaGetSymbolAddress((void**)&feat, g_feat);
    cudaGetSymbolAddress((void**)&gwp,  g_gw);
    cudaGetSymbolAddress((void**)&e1,   g_e1);

    k_conv1pool<<<BATCH, 144>>>(x, conv1_w, conv1_b, pool);
    k_conv2<<<BATCH, 160>>>(pool, conv2_w, conv2_b, feat);
    k_router<<<BATCH / 8, 256>>>(feat, Wg, bg, Wglu, bglu, gwp);
    dim3 g4(BATCH / 128, NEXP);
    k_gemm1<<<g4, 256>>>(feat, W1e, b1e, e1);
    k_expert2<<<BATCH / 32, 256>>>(e1, W2e, b2e, gwp, Ws, bs, out);
}

// round 8
// speedup vs baseline: 1.9521x; 1.9521x over previous
#include <cuda_runtime.h>
#include <cuda_bf16.h>
#include <math.h>
#include <stdint.h>

#define BATCH 8192
#define DIN   3200
#define DH    128
#define NEXP  5

// ---------------- scratch (static device memory; no allocation) ----------------
__device__ float g_pool[BATCH * 16 * 12 * 12];        // conv1+pool output  [B,16,12,12]
__device__ float g_feat[BATCH * DIN];                 // conv2 output       [B,3200] fp32
__device__ __nv_bfloat16 g_featbf[BATCH * DIN];       // conv2 output bf16
__device__ __nv_bfloat16 g_w1t[NEXP * DH * DIN];      // W1e transposed bf16 [5,128,3200]
__device__ float g_gw  [BATCH * NEXP];                // routing weights    [B,5]
__device__ float g_e1  [BATCH * NEXP * DH];           // expert layer-1     [B,5*128]

// =========================== PTX helpers (baseline ISA only) ====================
__device__ __forceinline__ uint32_t smem_u32(const void* p) {
    uint32_t a;
    asm("{ .reg .u64 t; cvta.to.shared.u64 t, %1; cvt.u32.u64 %0, t; }" : "=r"(a) : "l"(p));
    return a;
}
__device__ __forceinline__ void cp_async16(uint32_t dst, const void* src) {
    asm volatile("cp.async.cg.shared.global [%0], [%1], 16;" :: "r"(dst), "l"(src) : "memory");
}
#define CP_COMMIT() asm volatile("cp.async.commit_group;" ::: "memory")
#define CP_WAIT(n)  asm volatile("cp.async.wait_group %0;" :: "n"(n) : "memory")

__device__ __forceinline__ void ldsm_x4(uint32_t addr, uint32_t& r0, uint32_t& r1,
                                        uint32_t& r2, uint32_t& r3) {
    asm volatile("ldmatrix.sync.aligned.m8n8.x4.shared.b16 {%0,%1,%2,%3}, [%4];"
                 : "=r"(r0), "=r"(r1), "=r"(r2), "=r"(r3) : "r"(addr));
}
__device__ __forceinline__ void mma_bf16(float* d, const uint32_t* a, const uint32_t* b) {
    asm volatile("mma.sync.aligned.m16n8k16.row.col.f32.bf16.bf16.f32 "
                 "{%0,%1,%2,%3}, {%4,%5,%6,%7}, {%8,%9}, {%0,%1,%2,%3};"
                 : "+f"(d[0]), "+f"(d[1]), "+f"(d[2]), "+f"(d[3])
                 : "r"(a[0]), "r"(a[1]), "r"(a[2]), "r"(a[3]), "r"(b[0]), "r"(b[1]));
}

// ================= Kernel 1: conv1 (5x5 VALID) + ReLU + maxpool 2x2 =============
__global__ void k_conv1pool(const float* __restrict__ x,
                            const float* __restrict__ w,
                            const float* __restrict__ bias,
                            float* __restrict__ out) {
    __shared__ float s_img[784];
    __shared__ float s_w[400];
    __shared__ float s_b[16];
    int b = blockIdx.x;
    int tid = threadIdx.x;
    const float* xin = x + b * 784;
    for (int i = tid; i < 784; i += 144) s_img[i] = xin[i];
    for (int i = tid; i < 400; i += 144) s_w[i] = w[i];
    if (tid < 16) s_b[tid] = bias[tid];
    __syncthreads();

    int py = tid / 12, px = tid % 12;
    float xr[6][6];
#pragma unroll
    for (int r = 0; r < 6; r++)
#pragma unroll
        for (int c = 0; c < 6; c++)
            xr[r][c] = s_img[(2 * py + r) * 28 + 2 * px + c];

    float* o = out + (b * 16) * 144 + py * 12 + px;
#pragma unroll
    for (int ch = 0; ch < 16; ch++) {
        float bb = s_b[ch];
        float a00 = bb, a01 = bb, a10 = bb, a11 = bb;
        const float* wc = &s_w[ch * 25];
#pragma unroll
        for (int ky = 0; ky < 5; ky++)
#pragma unroll
            for (int kx = 0; kx < 5; kx++) {
                float wv = wc[ky * 5 + kx];
                a00 += wv * xr[ky][kx];
                a01 += wv * xr[ky][kx + 1];
                a10 += wv * xr[ky + 1][kx];
                a11 += wv * xr[ky + 1][kx + 1];
            }
        float m = fmaxf(fmaxf(a00, a01), fmaxf(a10, a11));
        o[ch * 144] = fmaxf(m, 0.0f);
    }
}

// ================= Kernel 2: conv2 (3x3 VALID) + ReLU -> feat (fp32 + bf16) =====
__global__ void k_conv2(const float* __restrict__ pool,
                        const float* __restrict__ w,
                        const float* __restrict__ bias,
                        float* __restrict__ feat,
                        __nv_bfloat16* __restrict__ featbf) {
    __shared__ float s_in[2304];
    __shared__ float s_w[4608];
    __shared__ float s_b[32];
    int b = blockIdx.x;
    int tid = threadIdx.x;
    const float* pin = pool + b * 2304;
    for (int i = tid; i < 2304; i += 160) s_in[i] = pin[i];
    for (int i = tid; i < 4608; i += 160) s_w[i] = w[i];
    if (tid < 32) s_b[tid] = bias[tid];
    __syncthreads();

    int ot = tid / 20;
    int pt = tid % 20;
    int ob = ot * 4;
    int oy = pt >> 1;
    int oxb = (pt & 1) * 5;

    float acc[4][5];
#pragma unroll
    for (int a = 0; a < 4; a++) {
        float bb = s_b[ob + a];
#pragma unroll
        for (int j = 0; j < 5; j++) acc[a][j] = bb;
    }

    for (int i = 0; i < 16; i++) {
#pragma unroll
        for (int ky = 0; ky < 3; ky++) {
            const float* ir = &s_in[(i * 12 + oy + ky) * 12 + oxb];
            float inr[7];
#pragma unroll
            for (int t = 0; t < 7; t++) inr[t] = ir[t];
#pragma unroll
            for (int kx = 0; kx < 3; kx++) {
                float wv[4];
#pragma unroll
                for (int a = 0; a < 4; a++)
                    wv[a] = s_w[((ob + a) * 16 + i) * 9 + ky * 3 + kx];
#pragma unroll
                for (int a = 0; a < 4; a++)
#pragma unroll
                    for (int j = 0; j < 5; j++)
                        acc[a][j] += wv[a] * inr[kx + j];
            }
        }
    }

    float* frow = feat + (size_t)b * DIN;
    __nv_bfloat16* fbrow = featbf + (size_t)b * DIN;
#pragma unroll
    for (int a = 0; a < 4; a++)
#pragma unroll
        for (int j = 0; j < 5; j++) {
            float v = fmaxf(acc[a][j], 0.0f);
            int idx = (ob + a) * 100 + oy * 10 + oxb + j;
            frow[idx] = v;
            fbrow[idx] = __float2bfloat16(v);
        }
}

// ================ Kernel 2b: W1e [5,3200,128] fp32 -> W1t [5,128,3200] bf16 =====
__global__ void k_w1_convert(const float* __restrict__ W1e,
                             __nv_bfloat16* __restrict__ W1t) {
    __shared__ float t[32][33];
    int e = blockIdx.z;
    int k0 = blockIdx.x * 32;
    int n0 = blockIdx.y * 32;
    int tx = threadIdx.x, ty = threadIdx.y;
    const float* Win = W1e + (size_t)e * DIN * DH;
    __nv_bfloat16* Wout = W1t + (size_t)e * DH * DIN;
#pragma unroll
    for (int yy = ty; yy < 32; yy += 8)
        t[yy][tx] = Win[(size_t)(k0 + yy) * DH + n0 + tx];
    __syncthreads();
#pragma unroll
    for (int yy = ty; yy < 32; yy += 8)
        Wout[(size_t)(n0 + yy) * DIN + k0 + tx] = __float2bfloat16(t[tx][yy]);
}

// ================= Kernel 3: GLU router + top-3 + softmax -> weights ============
__global__ void k_router(const float* __restrict__ feat,
                         const float* __restrict__ Wg,  const float* __restrict__ bg,
                         const float* __restrict__ Wgl, const float* __restrict__ bgl,
                         float* __restrict__ gw) {
    int warp = (blockIdx.x * blockDim.x + threadIdx.x) >> 5;
    int lane = threadIdx.x & 31;
    if (warp >= BATCH) return;
    const float* f = feat + (size_t)warp * DIN;
    float acc[10];
#pragma unroll
    for (int e = 0; e < 10; e++) acc[e] = 0.0f;
    for (int k = lane; k < DIN; k += 32) {
        float fv = f[k];
        const float* wg = Wg  + k * NEXP;
        const float* wl = Wgl + k * NEXP;
#pragma unroll
        for (int e = 0; e < NEXP; e++) {
            acc[e]     += fv * __ldg(&wg[e]);
            acc[5 + e] += fv * __ldg(&wl[e]);
        }
    }
#pragma unroll
    for (int off = 16; off; off >>= 1)
#pragma unroll
        for (int e = 0; e < 10; e++)
            acc[e] += __shfl_down_sync(0xFFFFFFFFu, acc[e], off);

    if (lane == 0) {
        float gate[NEXP];
#pragma unroll
        for (int e = 0; e < NEXP; e++) {
            float g = acc[e] + bg[e];
            float s = 1.0f / (1.0f + expf(-(acc[5 + e] + bgl[e])));
            gate[e] = g * s;
        }
        float v0 = -1e30f, v1 = -1e30f, v2 = -1e30f;
        int i0 = 0, i1 = 0, i2 = 0;
#pragma unroll
        for (int e = 0; e < NEXP; e++) {
            float g = gate[e];
            if (g > v0)      { v2 = v1; i2 = i1; v1 = v0; i1 = i0; v0 = g; i0 = e; }
            else if (g > v1) { v2 = v1; i2 = i1; v1 = g;  i1 = e; }
            else if (g > v2) { v2 = g;  i2 = e; }
        }
        float e0 = 1.0f;
        float e1 = expf(v1 - v0);
        float e2 = expf(v2 - v0);
        float inv = 1.0f / (e0 + e1 + e2);
        float wout[NEXP];
#pragma unroll
        for (int e = 0; e < NEXP; e++) wout[e] = 0.0f;
        wout[i0] = e0 * inv; wout[i1] = e1 * inv; wout[i2] = e2 * inv;
#pragma unroll
        for (int e = 0; e < NEXP; e++) gw[warp * NEXP + e] = wout[e];
    }
}

// ============ Kernel 4: e1 = tanh(feat @ W1e + b1e) — HMMA bf16 mma.sync ========
// grid (64, 5), 256 threads (8 warps, 4x2). CTA tile 128x128, BK=32, double-buffered
// cp.async. Both operands K-major; ldmatrix (non-trans) yields a- and b-frags.
#define BKC   32
#define NTC   (DIN / BKC)          // 100 k-chunks
#define PITCH 80                   // bytes per 32-bf16 row (64B data + 16B pad)

__global__ void __launch_bounds__(256, 2)
k_gemm1_mma(const __nv_bfloat16* __restrict__ A,     // [8192,3200]
            const __nv_bfloat16* __restrict__ Bt,    // [5,128,3200]
            const float* __restrict__ b1e,           // [5,128]
            float* __restrict__ E1) {                // [8192,640]
    __shared__ __align__(128) unsigned char s_A[2][128 * PITCH];
    __shared__ __align__(128) unsigned char s_B[2][128 * PITCH];

    int tid = threadIdx.x;
    int w = tid >> 5, lane = tid & 31;
    int wm = w & 3, wn = w >> 2;                     // warp tile: rows wm*32, cols wn*64
    int mb = blockIdx.x, e = blockIdx.y;

    const __nv_bfloat16* Ab = A  + (size_t)(mb * 128) * DIN;
    const __nv_bfloat16* Bb = Bt + (size_t)e * DH * DIN;

    uint32_t sA0 = smem_u32(s_A);
    uint32_t sB0 = smem_u32(s_B);

    float acc[2][8][4];
#pragma unroll
    for (int i = 0; i < 2; i++)
#pragma unroll
        for (int j = 0; j < 8; j++)
#pragma unroll
            for (int q = 0; q < 4; q++) acc[i][j][q] = 0.0f;

    // loader: 512 16B chunks per operand tile; thread f covers row f>>1, 16B-col (f&1)*2
    int lr = tid >> 1;               // 0..127
    int lc = (tid & 1) * 2;          // 16B-col base 0 or 2
    auto load_tile = [&](int t, int s) {
        int k0 = t * BKC;
        uint32_t aD = sA0 + s * (128 * PITCH) + lr * PITCH + lc * 16;
        uint32_t bD = sB0 + s * (128 * PITCH) + lr * PITCH + lc * 16;
        const __nv_bfloat16* aS = Ab + (size_t)lr * DIN + k0 + lc * 8;
        const __nv_bfloat16* bS = Bb + (size_t)lr * DIN + k0 + lc * 8;
        cp_async16(aD,      aS);
        cp_async16(aD + 16, aS + 8);
        cp_async16(bD,      bS);
        cp_async16(bD + 16, bS + 8);
    };

    load_tile(0, 0);
    CP_COMMIT();

    // ldmatrix lane addressing (row/k-byte offsets within a tile)
    int aRow = (lane & 7) + ((lane >> 3) & 1) * 8;   // + i*16 + wm*32
    int aKb  = (lane >> 4) * 16;                     // + ks*32
    int bRow = (lane & 7) + (lane >> 4) * 8;         // + j2*16 + wn*64
    int bKb  = ((lane >> 3) & 1) * 16;               // + ks*32

    for (int t = 0; t < NTC; t++) {
        int s = t & 1;
        if (t + 1 < NTC) { load_tile(t + 1, s ^ 1); CP_COMMIT(); }
        if (t + 1 < NTC) CP_WAIT(1); else CP_WAIT(0);
        __syncthreads();

        uint32_t aT = sA0 + s * (128 * PITCH);
        uint32_t bT = sB0 + s * (128 * PITCH);
#pragma unroll
        for (int ks = 0; ks < 2; ks++) {
            uint32_t a[2][4], b[8][2];
#pragma unroll
            for (int i = 0; i < 2; i++) {
                uint32_t addr = aT + (wm * 32 + i * 16 + aRow) * PITCH + ks * 32 + aKb;
                ldsm_x4(addr, a[i][0], a[i][1], a[i][2], a[i][3]);
            }
#pragma unroll
            for (int j2 = 0; j2 < 4; j2++) {
                uint32_t addr = bT + (wn * 64 + j2 * 16 + bRow) * PITCH + ks * 32 + bKb;
                ldsm_x4(addr, b[2 * j2][0], b[2 * j2][1], b[2 * j2 + 1][0], b[2 * j2 + 1][1]);
            }
#pragma unroll
            for (int i = 0; i < 2; i++)
#pragma unroll
                for (int j = 0; j < 8; j++)
                    mma_bf16(acc[i][j], a[i], b[j]);
        }
        __syncthreads();
    }

    // epilogue: bias + tanh, write E1[m, e*128 + n]
    const float* bias = b1e + e * DH;
    int qr = lane >> 2;                // row within 8
    int qc = (lane & 3) * 2;           // col pair within 8
#pragma unroll
    for (int i = 0; i < 2; i++) {
        int m0 = mb * 128 + wm * 32 + i * 16 + qr;
#pragma unroll
        for (int j = 0; j < 8; j++) {
            int c = wn * 64 + j * 8 + qc;
            float b0 = __ldg(&bias[c]);
            float b1 = __ldg(&bias[c + 1]);
            float2 v0 = { tanhf(acc[i][j][0] + b0), tanhf(acc[i][j][1] + b1) };
            float2 v1 = { tanhf(acc[i][j][2] + b0), tanhf(acc[i][j][3] + b1) };
            *reinterpret_cast<float2*>(&E1[(size_t)m0 * (NEXP * DH) + e * DH + c]) = v0;
            *reinterpret_cast<float2*>(&E1[(size_t)(m0 + 8) * (NEXP * DH) + e * DH + c]) = v1;
        }
    }
}

// ====== Kernel 5: e2 = tanh(e1 @ W2e + b2e); moe = sum_e w_e*e2; head; softmax ==
__global__ void k_expert2(const float* __restrict__ E1,
                          const float* __restrict__ W2e,
                          const float* __restrict__ b2e,
                          const float* __restrict__ gw,
                          const float* __restrict__ Ws,
                          const float* __restrict__ bs,
                          float* __restrict__ out) {
    __shared__ float s_e1[32][128];
    __shared__ float s_w2[32][128];
    __shared__ float s_gw[32][5];
    __shared__ float s_ws[1280];
    __shared__ float s_log[32][10];

    int b0 = blockIdx.x * 32;
    int tid = threadIdx.x;
    int h  = tid & 127;
    int rb = (tid >> 7) * 16;

    for (int i = tid; i < 160; i += 256)
        s_gw[i / 5][i % 5] = gw[(b0 + i / 5) * NEXP + (i % 5)];
    for (int i = tid; i < 1280; i += 256) s_ws[i] = Ws[i];

    float moe[16];
#pragma unroll
    for (int r = 0; r < 16; r++) moe[r] = 0.0f;

    for (int e = 0; e < NEXP; e++) {
        __syncthreads();
        for (int i = tid; i < 4096; i += 256) {
            int r = i >> 7, hh = i & 127;
            s_e1[r][hh] = E1[(size_t)(b0 + r) * (NEXP * DH) + e * DH + hh];
        }
        float pre[16];
        float bias = b2e[e * DH + h];
#pragma unroll
        for (int r = 0; r < 16; r++) pre[r] = bias;

        for (int hc = 0; hc < 4; hc++) {
            __syncthreads();
            for (int i = tid; i < 4096; i += 256) {
                int hi = i >> 7, hh = i & 127;
                s_w2[hi][hh] = W2e[(size_t)e * DH * DH + (hc * 32 + hi) * DH + hh];
            }
            __syncthreads();
#pragma unroll 8
            for (int hi = 0; hi < 32; hi++) {
                float wv = s_w2[hi][h];
#pragma unroll
                for (int r = 0; r < 16; r++)
                    pre[r] += s_e1[rb + r][hc * 32 + hi] * wv;
            }
        }
        float we[16];
#pragma unroll
        for (int r = 0; r < 16; r++) we[r] = s_gw[rb + r][e];
#pragma unroll
        for (int r = 0; r < 16; r++)
            moe[r] += we[r] * tanhf(pre[r]);
    }

    __syncthreads();
#pragma unroll
    for (int r = 0; r < 16; r++) s_w2[rb + r][h] = moe[r];
    __syncthreads();

    for (int i = tid; i < 320; i += 256) {
        int r = i / 10, c = i % 10;
        float a = bs[c];
#pragma unroll 16
        for (int hh = 0; hh < 128; hh++)
            a += s_w2[r][hh] * s_ws[hh * 10 + c];
        s_log[r][c] = a;
    }
    __syncthreads();
    if (tid < 32) {
        int r = tid;
        float m = -1e30f;
#pragma unroll
        for (int c = 0; c < 10; c++) m = fmaxf(m, s_log[r][c]);
        float ex[10], s = 0.0f;
#pragma unroll
        for (int c = 0; c < 10; c++) { ex[c] = expf(s_log[r][c] - m); s += ex[c]; }
        float inv = 1.0f / s;
        float* orow = out + (size_t)(b0 + r) * 10;
#pragma unroll
        for (int c = 0; c < 10; c++) orow[c] = ex[c] * inv;
    }
}

// =============================== launcher =======================================
extern "C" void kernel_launch(void* const* d_in, const int* in_sizes, int n_in,
                              void* d_out, int out_size) {
    const float* x       = (const float*)d_in[0];
    const float* conv1_w = (const float*)d_in[1];
    const float* conv1_b = (const float*)d_in[2];
    const float* conv2_w = (const float*)d_in[3];
    const float* conv2_b = (const float*)d_in[4];
    const float* Wg      = (const float*)d_in[5];
    const float* bg      = (const float*)d_in[6];
    const float* Wglu    = (const float*)d_in[7];
    const float* bglu    = (const float*)d_in[8];
    const float* W1e     = (const float*)d_in[9];
    const float* b1e     = (const float*)d_in[10];
    const float* W2e     = (const float*)d_in[11];
    const float* b2e     = (const float*)d_in[12];
    const float* Ws      = (const float*)d_in[13];
    const float* bs      = (const float*)d_in[14];
    float* out = (float*)d_out;

    float *pool, *feat, *gwp, *e1;
    __nv_bfloat16 *featbf, *w1t;
    cudaGetSymbolAddress((void**)&pool,   g_pool);
    cudaGetSymbolAddress((void**)&feat,   g_feat);
    cudaGetSymbolAddress((void**)&featbf, g_featbf);
    cudaGetSymbolAddress((void**)&w1t,    g_w1t);
    cudaGetSymbolAddress((void**)&gwp,    g_gw);
    cudaGetSymbolAddress((void**)&e1,     g_e1);

    dim3 gW(DIN / 32, DH / 32, NEXP);
    k_w1_convert<<<gW, dim3(32, 8)>>>(W1e, w1t);
    k_conv1pool<<<BATCH, 144>>>(x, conv1_w, conv1_b, pool);
    k_conv2<<<BATCH, 160>>>(pool, conv2_w, conv2_b, feat, featbf);
    k_router<<<BATCH / 8, 256>>>(feat, Wg, bg, Wglu, bglu, gwp);
    dim3 g4(BATCH / 128, NEXP);
    k_gemm1_mma<<<g4, 256>>>(featbf, w1t, b1e, e1);
    k_expert2<<<BATCH / 32, 256>>>(e1, W2e, b2e, gwp, Ws, bs, out);
}

// round 11
// speedup vs baseline: 2.6858x; 1.3759x over previous
#include <cuda_runtime.h>
#include <cuda_bf16.h>
#include <math.h>
#include <stdint.h>

#define BATCH 8192
#define DIN   3200
#define DH    128
#define NEXP  5
#define CHP   24      // channel pitch for pool tiles (48B rows: 16B-aligned, conflict-free)

// ---------------- scratch (static device memory; no allocation) ----------------
__device__ __nv_bfloat16 g_poolt_h[BATCH * 144 * CHP]; // conv1 out hi [B][pos][24]
__device__ __nv_bfloat16 g_poolt_l[BATCH * 144 * CHP]; // conv1 out lo
__device__ float g_feat[BATCH * DIN];                  // conv2 output fp32 (router)
__device__ __nv_bfloat16 g_featbf[BATCH * DIN];        // conv2 output bf16 (gemm1)
__device__ __nv_bfloat16 g_w1t[NEXP * DH * DIN];       // W1e transposed bf16
__device__ float g_wgT[10 * DIN];                      // [Wg|Wglu]^T fp32
__device__ float g_gw  [BATCH * NEXP];                 // routing weights [B,5]
__device__ float g_e1  [BATCH * NEXP * DH];            // expert layer-1  [B,640]

// =========================== PTX helpers (baseline ISA only) ====================
__device__ __forceinline__ uint32_t smem_u32(const void* p) {
    uint32_t a;
    asm("{ .reg .u64 t; cvta.to.shared.u64 t, %1; cvt.u32.u64 %0, t; }" : "=r"(a) : "l"(p));
    return a;
}
__device__ __forceinline__ void cp_async16(uint32_t dst, const void* src) {
    asm volatile("cp.async.cg.shared.global [%0], [%1], 16;" :: "r"(dst), "l"(src) : "memory");
}
#define CP_COMMIT() asm volatile("cp.async.commit_group;" ::: "memory")
#define CP_WAIT(n)  asm volatile("cp.async.wait_group %0;" :: "n"(n) : "memory")

__device__ __forceinline__ void ldsm_x4(uint32_t addr, uint32_t& r0, uint32_t& r1,
                                        uint32_t& r2, uint32_t& r3) {
    asm volatile("ldmatrix.sync.aligned.m8n8.x4.shared.b16 {%0,%1,%2,%3}, [%4];"
                 : "=r"(r0), "=r"(r1), "=r"(r2), "=r"(r3) : "r"(addr));
}
__device__ __forceinline__ void mma_bf16(float* d, const uint32_t* a, const uint32_t* b) {
    asm volatile("mma.sync.aligned.m16n8k16.row.col.f32.bf16.bf16.f32 "
                 "{%0,%1,%2,%3}, {%4,%5,%6,%7}, {%8,%9}, {%0,%1,%2,%3};"
                 : "+f"(d[0]), "+f"(d[1]), "+f"(d[2]), "+f"(d[3])
                 : "r"(a[0]), "r"(a[1]), "r"(a[2]), "r"(a[3]), "r"(b[0]), "r"(b[1]));
}
__device__ __forceinline__ uint32_t bf16pack(float a, float b) {
    return (uint32_t)__bfloat16_as_ushort(__float2bfloat16(a)) |
           ((uint32_t)__bfloat16_as_ushort(__float2bfloat16(b)) << 16);
}

// ================= Kernel 1: conv1 (5x5) + ReLU + maxpool -> pool_t hi/lo =======
// grid = BATCH, block = 144. Output layout [b][pos=py*12+px][CHP] (16 ch used).
__global__ void k_conv1pool(const float* __restrict__ x,
                            const float* __restrict__ w,
                            const float* __restrict__ bias,
                            __nv_bfloat16* __restrict__ ph,
                            __nv_bfloat16* __restrict__ pl) {
    __shared__ float s_img[784];
    __shared__ float s_w[400];
    __shared__ float s_b[16];
    int b = blockIdx.x;
    int tid = threadIdx.x;
    const float* xin = x + b * 784;
    for (int i = tid; i < 784; i += 144) s_img[i] = xin[i];
    for (int i = tid; i < 400; i += 144) s_w[i] = w[i];
    if (tid < 16) s_b[tid] = bias[tid];
    __syncthreads();

    int py = tid / 12, px = tid % 12;
    float xr[6][6];
#pragma unroll
    for (int r = 0; r < 6; r++)
#pragma unroll
        for (int c = 0; c < 6; c++)
            xr[r][c] = s_img[(2 * py + r) * 28 + 2 * px + c];

    float v[16];
#pragma unroll
    for (int ch = 0; ch < 16; ch++) {
        float bb = s_b[ch];
        float a00 = bb, a01 = bb, a10 = bb, a11 = bb;
        const float* wc = &s_w[ch * 25];
#pragma unroll
        for (int ky = 0; ky < 5; ky++)
#pragma unroll
            for (int kx = 0; kx < 5; kx++) {
                float wv = wc[ky * 5 + kx];
                a00 += wv * xr[ky][kx];
                a01 += wv * xr[ky][kx + 1];
                a10 += wv * xr[ky + 1][kx];
                a11 += wv * xr[ky + 1][kx + 1];
            }
        v[ch] = fmaxf(fmaxf(fmaxf(a00, a01), fmaxf(a10, a11)), 0.0f);
    }

    int pbase = (b * 144 + py * 12 + px) * CHP;
#pragma unroll
    for (int ch = 0; ch < 16; ch += 2) {
        __nv_bfloat16 h0 = __float2bfloat16(v[ch]);
        __nv_bfloat16 h1 = __float2bfloat16(v[ch + 1]);
        float h0f = __bfloat162float(h0), h1f = __bfloat162float(h1);
        *(uint32_t*)(ph + pbase + ch) =
            (uint32_t)__bfloat16_as_ushort(h0) | ((uint32_t)__bfloat16_as_ushort(h1) << 16);
        *(uint32_t*)(pl + pbase + ch) = bf16pack(v[ch] - h0f, v[ch + 1] - h1f);
    }
}

// ====== Kernel 2: conv2 via HMMA implicit conv, 3-pass split-bf16 (fp32-exact) ==
// grid = BATCH/2, 256 threads (8 warps). Warp -> (img = w>>2, quarter = w&3).
// smem: POOLH/POOLL (2 img x 144 x 24 bf16), BHO/BLO ([9][32][24] bf16),
// OUTF overlaps pool+weights (all consumed before staging; guarded by barrier).
#define C2_POOLH 0
#define C2_POOLL 13824
#define C2_BHO   27648
#define C2_BLO   41472
#define C2_OUTF  0
#define C2_BIAS  55296
#define C2_SMEM  55424
__global__ void __launch_bounds__(256)
k_conv2_mma(const __nv_bfloat16* __restrict__ ph,
            const __nv_bfloat16* __restrict__ pl,
            const float* __restrict__ w2,     // [32][16][3][3]
            const float* __restrict__ bias,
            float* __restrict__ feat,
            __nv_bfloat16* __restrict__ featbf) {
    extern __shared__ __align__(16) unsigned char sm[];
    uint32_t sb = smem_u32(sm);
    int tid = threadIdx.x;
    int w8 = tid >> 5, lane = tid & 31;
    int b0 = blockIdx.x * 2;
    int img = w8 >> 2;
    int wbase = (w8 & 3) * 32;

    // pool hi/lo -> smem: 2 img x 2 planes x 432 16B-chunks = 1728
    for (int c = tid; c < 1728; c += 256) {
        int im = c / 864; int r = c % 864; int plane = r / 432; int off = (r % 432) * 16;
        uint32_t dst = sb + (plane ? C2_POOLL : C2_POOLH) + im * 6912 + off;
        const __nv_bfloat16* src = (plane ? pl : ph) + (size_t)(b0 + im) * (144 * CHP);
        cp_async16(dst, (const char*)src + off);
    }
    CP_COMMIT();

    // weights -> smem, [tap][oc][CHP] hi/lo split
    for (int i = tid; i < 4608; i += 256) {
        int tap = i >> 9; int oc = (i >> 4) & 31; int ch = i & 15;
        float v = w2[(oc * 16 + ch) * 9 + tap];
        __nv_bfloat16 h = __float2bfloat16(v);
        int off = ((tap * 32 + oc) * CHP + ch) * 2;
        *(__nv_bfloat16*)(sm + C2_BHO + off) = h;
        *(__nv_bfloat16*)(sm + C2_BLO + off) = __float2bfloat16(v - __bfloat162float(h));
    }
    if (tid < 32) *(float*)(sm + C2_BIAS + tid * 4) = bias[tid];
    CP_WAIT(0);
    __syncthreads();

    // per-lane ldmatrix addresses (row stride 48B = 16B-aligned)
    int posIdx[2];
#pragma unroll
    for (int mi = 0; mi < 2; mi++) {
        int pos = wbase + mi * 16 + (lane & 15);
        pos = min(pos, 99);
        posIdx[mi] = (pos / 10) * 12 + (pos % 10);
    }
    int chOff = (lane >> 4) * 16;
    uint32_t aBaseH = sb + C2_POOLH + img * 6912 + chOff;
    uint32_t aBaseL = sb + C2_POOLL + img * 6912 + chOff;
    int bRow = (lane & 7) + (lane >> 4) * 8;
    int bKb = ((lane >> 3) & 1) * 16;
    uint32_t bBaseH = sb + C2_BHO + bRow * (CHP * 2) + bKb;
    uint32_t bBaseL = sb + C2_BLO + bRow * (CHP * 2) + bKb;

    float acc[2][4][4];
#pragma unroll
    for (int i = 0; i < 2; i++)
#pragma unroll
        for (int j = 0; j < 4; j++)
#pragma unroll
            for (int q = 0; q < 4; q++) acc[i][j][q] = 0.0f;

    const int tapOff[9] = {0, 1, 2, 12, 13, 14, 24, 25, 26};
#pragma unroll
    for (int tap = 0; tap < 9; tap++) {
        int to = tapOff[tap] * (CHP * 2);
        uint32_t ah[2][4], al[2][4], bh[4][2], bl[4][2];
#pragma unroll
        for (int mi = 0; mi < 2; mi++) {
            ldsm_x4(aBaseH + posIdx[mi] * (CHP * 2) + to, ah[mi][0], ah[mi][1], ah[mi][2], ah[mi][3]);
            ldsm_x4(aBaseL + posIdx[mi] * (CHP * 2) + to, al[mi][0], al[mi][1], al[mi][2], al[mi][3]);
        }
#pragma unroll
        for (int j2 = 0; j2 < 2; j2++) {
            uint32_t off = (tap * 32 + j2 * 16) * (CHP * 2);
            ldsm_x4(bBaseH + off, bh[2 * j2][0], bh[2 * j2][1], bh[2 * j2 + 1][0], bh[2 * j2 + 1][1]);
            ldsm_x4(bBaseL + off, bl[2 * j2][0], bl[2 * j2][1], bl[2 * j2 + 1][0], bl[2 * j2 + 1][1]);
        }
#pragma unroll
        for (int mi = 0; mi < 2; mi++)
#pragma unroll
            for (int nj = 0; nj < 4; nj++) {
                mma_bf16(acc[mi][nj], ah[mi], bh[nj]);
                mma_bf16(acc[mi][nj], ah[mi], bl[nj]);
                mma_bf16(acc[mi][nj], al[mi], bh[nj]);
            }
    }

    __syncthreads();   // all smem reads done — OUTF may now overwrite pool/weights

    // stage (bias + relu) into fp32 smem [img][oc][113]
#pragma unroll
    for (int mi = 0; mi < 2; mi++) {
        int pr = wbase + mi * 16 + (lane >> 2);
#pragma unroll
        for (int nj = 0; nj < 4; nj++) {
            int c0 = nj * 8 + (lane & 3) * 2;
            float bb0 = *(float*)(sm + C2_BIAS + c0 * 4);
            float bb1 = *(float*)(sm + C2_BIAS + (c0 + 1) * 4);
            float* o = (float*)(sm + C2_OUTF) + img * 3616;
            if (pr < 100) {
                o[c0 * 113 + pr]       = fmaxf(acc[mi][nj][0] + bb0, 0.0f);
                o[(c0 + 1) * 113 + pr] = fmaxf(acc[mi][nj][1] + bb1, 0.0f);
            }
            if (pr + 8 < 100) {
                o[c0 * 113 + pr + 8]       = fmaxf(acc[mi][nj][2] + bb0, 0.0f);
                o[(c0 + 1) * 113 + pr + 8] = fmaxf(acc[mi][nj][3] + bb1, 0.0f);
            }
        }
    }
    __syncthreads();

    // coalesced writeout: feat fp32 + featbf bf16
    for (int i = tid; i < 3200; i += 256) {
        int im = i / 1600;
        int p2 = i - im * 1600;
        int oc = p2 / 50;
        int pos = (p2 - oc * 50) * 2;
        const float* o = (const float*)(sm + C2_OUTF) + im * 3616 + oc * 113 + pos;
        float v0 = o[0], v1 = o[1];
        size_t g = (size_t)(b0 + im) * DIN + oc * 100 + pos;
        float2 fv = {v0, v1};
        *(float2*)(feat + g) = fv;
        *(uint32_t*)(featbf + g) = bf16pack(v0, v1);
    }
}

// ================ Kernel 2b: W1e [5,3200,128] fp32 -> W1t [5,128,3200] bf16 =====
__global__ void k_w1_convert(const float* __restrict__ W1e,
                             __nv_bfloat16* __restrict__ W1t) {
    __shared__ float t[32][33];
    int e = blockIdx.z;
    int k0 = blockIdx.x * 32;
    int n0 = blockIdx.y * 32;
    int tx = threadIdx.x, ty = threadIdx.y;
    const float* Win = W1e + (size_t)e * DIN * DH;
    __nv_bfloat16* Wout = W1t + (size_t)e * DH * DIN;
#pragma unroll
    for (int yy = ty; yy < 32; yy += 8)
        t[yy][tx] = Win[(size_t)(k0 + yy) * DH + n0 + tx];
    __syncthreads();
#pragma unroll
    for (int yy = ty; yy < 32; yy += 8)
        Wout[(size_t)(n0 + yy) * DIN + k0 + tx] = __float2bfloat16(t[tx][yy]);
}

// ================ Kernel 2c: [Wg|Wglu] -> wgT [10][3200] fp32 ===================
__global__ void k_wgt(const float* __restrict__ Wg, const float* __restrict__ Wgl,
                      float* __restrict__ wgT) {
    int i = blockIdx.x * 256 + threadIdx.x;
    if (i >= 10 * DIN) return;
    int e = i / DIN, k = i % DIN;
    wgT[i] = (e < 5) ? Wg[k * 5 + e] : Wgl[k * 5 + (e - 5)];
}

// ================= Kernel 3: GLU router (fp32, coalesced) =======================
__global__ void k_router(const float* __restrict__ feat,
                         const float* __restrict__ wgT,
                         const float* __restrict__ bg, const float* __restrict__ bgl,
                         float* __restrict__ gw) {
    int warp = (blockIdx.x * blockDim.x + threadIdx.x) >> 5;
    int lane = threadIdx.x & 31;
    if (warp >= BATCH) return;
    const float4* f4 = (const float4*)(feat + (size_t)warp * DIN);
    float acc[10];
#pragma unroll
    for (int e = 0; e < 10; e++) acc[e] = 0.0f;
#pragma unroll 5
    for (int it = 0; it < 25; it++) {
        int k4 = it * 32 + lane;
        float4 fv = f4[k4];
#pragma unroll
        for (int e = 0; e < 10; e++) {
            float4 wv = ((const float4*)(wgT + e * DIN))[k4];
            acc[e] += fv.x * wv.x + fv.y * wv.y + fv.z * wv.z + fv.w * wv.w;
        }
    }
#pragma unroll
    for (int off = 16; off; off >>= 1)
#pragma unroll
        for (int e = 0; e < 10; e++)
            acc[e] += __shfl_down_sync(0xFFFFFFFFu, acc[e], off);

    if (lane == 0) {
        float gate[NEXP];
#pragma unroll
        for (int e = 0; e < NEXP; e++) {
            float g = acc[e] + bg[e];
            float s = 1.0f / (1.0f + expf(-(acc[5 + e] + bgl[e])));
            gate[e] = g * s;
        }
        float v0 = -1e30f, v1 = -1e30f, v2 = -1e30f;
        int i0 = 0, i1 = 0, i2 = 0;
#pragma unroll
        for (int e = 0; e < NEXP; e++) {
            float g = gate[e];
            if (g > v0)      { v2 = v1; i2 = i1; v1 = v0; i1 = i0; v0 = g; i0 = e; }
            else if (g > v1) { v2 = v1; i2 = i1; v1 = g;  i1 = e; }
            else if (g > v2) { v2 = g;  i2 = e; }
        }
        float e1 = expf(v1 - v0);
        float e2 = expf(v2 - v0);
        float inv = 1.0f / (1.0f + e1 + e2);
        float wout[NEXP];
#pragma unroll
        for (int e = 0; e < NEXP; e++) wout[e] = 0.0f;
        wout[i0] = inv; wout[i1] = e1 * inv; wout[i2] = e2 * inv;
#pragma unroll
        for (int e = 0; e < NEXP; e++) gw[warp * NEXP + e] = wout[e];
    }
}

// ============ Kernel 4: e1 = tanh(feat @ W1e + b1e) — HMMA bf16 mma.sync ========
#define BKC   32
#define NTC   (DIN / BKC)
#define PITCH 80
__global__ void __launch_bounds__(256, 2)
k_gemm1_mma(const __nv_bfloat16* __restrict__ A,
            const __nv_bfloat16* __restrict__ Bt,
            const float* __restrict__ b1e,
            float* __restrict__ E1) {
    __shared__ __align__(128) unsigned char s_A[2][128 * PITCH];
    __shared__ __align__(128) unsigned char s_B[2][128 * PITCH];

    int tid = threadIdx.x;
    int w = tid >> 5, lane = tid & 31;
    int wm = w & 3, wn = w >> 2;
    int mb = blockIdx.x, e = blockIdx.y;

    const __nv_bfloat16* Ab = A  + (size_t)(mb * 128) * DIN;
    const __nv_bfloat16* Bb = Bt + (size_t)e * DH * DIN;

    uint32_t sA0 = smem_u32(s_A);
    uint32_t sB0 = smem_u32(s_B);

    float acc[2][8][4];
#pragma unroll
    for (int i = 0; i < 2; i++)
#pragma unroll
        for (int j = 0; j < 8; j++)
#pragma unroll
            for (int q = 0; q < 4; q++) acc[i][j][q] = 0.0f;

    int lr = tid >> 1;
    int lc = (tid & 1) * 2;
    auto load_tile = [&](int t, int s) {
        int k0 = t * BKC;
        uint32_t aD = sA0 + s * (128 * PITCH) + lr * PITCH + lc * 16;
        uint32_t bD = sB0 + s * (128 * PITCH) + lr * PITCH + lc * 16;
        const __nv_bfloat16* aS = Ab + (size_t)lr * DIN + k0 + lc * 8;
        const __nv_bfloat16* bS = Bb + (size_t)lr * DIN + k0 + lc * 8;
        cp_async16(aD,      aS);
        cp_async16(aD + 16, aS + 8);
        cp_async16(bD,      bS);
        cp_async16(bD + 16, bS + 8);
    };

    load_tile(0, 0);
    CP_COMMIT();

    int aRow = (lane & 7) + ((lane >> 3) & 1) * 8;
    int aKb  = (lane >> 4) * 16;
    int bRow = (lane & 7) + (lane >> 4) * 8;
    int bKb  = ((lane >> 3) & 1) * 16;

    for (int t = 0; t < NTC; t++) {
        int s = t & 1;
        if (t + 1 < NTC) { load_tile(t + 1, s ^ 1); CP_COMMIT(); }
        if (t + 1 < NTC) CP_WAIT(1); else CP_WAIT(0);
        __syncthreads();

        uint32_t aT = sA0 + s * (128 * PITCH);
        uint32_t bT = sB0 + s * (128 * PITCH);
#pragma unroll
        for (int ks = 0; ks < 2; ks++) {
            uint32_t a[2][4], b[8][2];
#pragma unroll
            for (int i = 0; i < 2; i++) {
                uint32_t addr = aT + (wm * 32 + i * 16 + aRow) * PITCH + ks * 32 + aKb;
                ldsm_x4(addr, a[i][0], a[i][1], a[i][2], a[i][3]);
            }
#pragma unroll
            for (int j2 = 0; j2 < 4; j2++) {
                uint32_t addr = bT + (wn * 64 + j2 * 16 + bRow) * PITCH + ks * 32 + bKb;
                ldsm_x4(addr, b[2 * j2][0], b[2 * j2][1], b[2 * j2 + 1][0], b[2 * j2 + 1][1]);
            }
#pragma unroll
            for (int i = 0; i < 2; i++)
#pragma unroll
                for (int j = 0; j < 8; j++)
                    mma_bf16(acc[i][j], a[i], b[j]);
        }
        __syncthreads();
    }

    const float* bias = b1e + e * DH;
    int qr = lane >> 2;
    int qc = (lane & 3) * 2;
#pragma unroll
    for (int i = 0; i < 2; i++) {
        int m0 = mb * 128 + wm * 32 + i * 16 + qr;
#pragma unroll
        for (int j = 0; j < 8; j++) {
            int c = wn * 64 + j * 8 + qc;
            float b0 = __ldg(&bias[c]);
            float b1 = __ldg(&bias[c + 1]);
            float2 v0 = { tanhf(acc[i][j][0] + b0), tanhf(acc[i][j][1] + b1) };
            float2 v1 = { tanhf(acc[i][j][2] + b0), tanhf(acc[i][j][3] + b1) };
            *reinterpret_cast<float2*>(&E1[(size_t)m0 * (NEXP * DH) + e * DH + c]) = v0;
            *reinterpret_cast<float2*>(&E1[(size_t)(m0 + 8) * (NEXP * DH) + e * DH + c]) = v1;
        }
    }
}

// ====== Kernel 5: e2 = tanh(e1 @ W2e + b2e); moe; head; softmax =================
__global__ void k_expert2(const float* __restrict__ E1,
                          const float* __restrict__ W2e,
                          const float* __restrict__ b2e,
                          const float* __restrict__ gw,
                          const float* __restrict__ Ws,
                          const float* __restrict__ bs,
                          float* __restrict__ out) {
    __shared__ float s_e1[32][128];
    __shared__ float s_w2[32][128];
    __shared__ float s_gw[32][5];
    __shared__ float s_ws[1280];
    __shared__ float s_log[32][10];

    int b0 = blockIdx.x * 32;
    int tid = threadIdx.x;
    int h  = tid & 127;
    int rb = (tid >> 7) * 16;

    for (int i = tid; i < 160; i += 256)
        s_gw[i / 5][i % 5] = gw[(b0 + i / 5) * NEXP + (i % 5)];
    for (int i = tid; i < 1280; i += 256) s_ws[i] = Ws[i];

    float moe[16];
#pragma unroll
    for (int r = 0; r < 16; r++) moe[r] = 0.0f;

    for (int e = 0; e < NEXP; e++) {
        __syncthreads();
        for (int i = tid; i < 4096; i += 256) {
            int r = i >> 7, hh = i & 127;
            s_e1[r][hh] = E1[(size_t)(b0 + r) * (NEXP * DH) + e * DH + hh];
        }
        float pre[16];
        float bias = b2e[e * DH + h];
#pragma unroll
        for (int r = 0; r < 16; r++) pre[r] = bias;

        for (int hc = 0; hc < 4; hc++) {
            __syncthreads();
            for (int i = tid; i < 4096; i += 256) {
                int hi = i >> 7, hh = i & 127;
                s_w2[hi][hh] = W2e[(size_t)e * DH * DH + (hc * 32 + hi) * DH + hh];
            }
            __syncthreads();
#pragma unroll 8
            for (int hi = 0; hi < 32; hi++) {
                float wv = s_w2[hi][h];
#pragma unroll
                for (int r = 0; r < 16; r++)
                    pre[r] += s_e1[rb + r][hc * 32 + hi] * wv;
            }
        }
        float we[16];
#pragma unroll
        for (int r = 0; r < 16; r++) we[r] = s_gw[rb + r][e];
#pragma unroll
        for (int r = 0; r < 16; r++)
            moe[r] += we[r] * tanhf(pre[r]);
    }

    __syncthreads();
#pragma unroll
    for (int r = 0; r < 16; r++) s_w2[rb + r][h] = moe[r];
    __syncthreads();

    for (int i = tid; i < 320; i += 256) {
        int r = i / 10, c = i % 10;
        float a = bs[c];
#pragma unroll 16
        for (int hh = 0; hh < 128; hh++)
            a += s_w2[r][hh] * s_ws[hh * 10 + c];
        s_log[r][c] = a;
    }
    __syncthreads();
    if (tid < 32) {
        int r = tid;
        float m = -1e30f;
#pragma unroll
        for (int c = 0; c < 10; c++) m = fmaxf(m, s_log[r][c]);
        float ex[10], s = 0.0f;
#pragma unroll
        for (int c = 0; c < 10; c++) { ex[c] = expf(s_log[r][c] - m); s += ex[c]; }
        float inv = 1.0f / s;
        float* orow = out + (size_t)(b0 + r) * 10;
#pragma unroll
        for (int c = 0; c < 10; c++) orow[c] = ex[c] * inv;
    }
}

// =============================== launcher =======================================
extern "C" void kernel_launch(void* const* d_in, const int* in_sizes, int n_in,
                              void* d_out, int out_size) {
    const float* x       = (const float*)d_in[0];
    const float* conv1_w = (const float*)d_in[1];
    const float* conv1_b = (const float*)d_in[2];
    const float* conv2_w = (const float*)d_in[3];
    const float* conv2_b = (const float*)d_in[4];
    const float* Wg      = (const float*)d_in[5];
    const float* bg      = (const float*)d_in[6];
    const float* Wglu    = (const float*)d_in[7];
    const float* bglu    = (const float*)d_in[8];
    const float* W1e     = (const float*)d_in[9];
    const float* b1e     = (const float*)d_in[10];
    const float* W2e     = (const float*)d_in[11];
    const float* b2e     = (const float*)d_in[12];
    const float* Ws      = (const float*)d_in[13];
    const float* bs      = (const float*)d_in[14];
    float* out = (float*)d_out;

    float *feat, *wgT, *gwp, *e1;
    __nv_bfloat16 *poolh, *pooll, *featbf, *w1t;
    cudaGetSymbolAddress((void**)&poolh,  g_poolt_h);
    cudaGetSymbolAddress((void**)&pooll,  g_poolt_l);
    cudaGetSymbolAddress((void**)&feat,   g_feat);
    cudaGetSymbolAddress((void**)&featbf, g_featbf);
    cudaGetSymbolAddress((void**)&w1t,    g_w1t);
    cudaGetSymbolAddress((void**)&wgT,    g_wgT);
    cudaGetSymbolAddress((void**)&gwp,    g_gw);
    cudaGetSymbolAddress((void**)&e1,     g_e1);

    cudaFuncSetAttribute(k_conv2_mma, cudaFuncAttributeMaxDynamicSharedMemorySize, C2_SMEM);

    k_wgt<<<(10 * DIN + 255) / 256, 256>>>(Wg, Wglu, wgT);
    dim3 gW(DIN / 32, DH / 32, NEXP);
    k_w1_convert<<<gW, dim3(32, 8)>>>(W1e, w1t);
    k_conv1pool<<<BATCH, 144>>>(x, conv1_w, conv1_b, poolh, pooll);
    k_conv2_mma<<<BATCH / 2, 256, C2_SMEM>>>(poolh, pooll, conv2_w, conv2_b, feat, featbf);
    k_router<<<BATCH / 8, 256>>>(feat, wgT, bg, bglu, gwp);
    dim3 g4(BATCH / 128, NEXP);
    k_gemm1_mma<<<g4, 256>>>(featbf, w1t, b1e, e1);
    k_expert2<<<BATCH / 32, 256>>>(e1, W2e, b2e, gwp, Ws, bs, out);
}

// round 12
// speedup vs baseline: 2.9586x; 1.1016x over previous
#include <cuda_runtime.h>
#include <cuda_bf16.h>
#include <math.h>
#include <stdint.h>

#define BATCH 8192
#define DIN   3200
#define DH    128
#define NEXP  5
#define CHP   24      // channel pitch for pool tiles (48B rows: 16B-aligned, conflict-free)

// ---------------- scratch (static device memory; no allocation) ----------------
__device__ __nv_bfloat16 g_poolt_h[BATCH * 144 * CHP]; // conv1 out hi [B][pos][24]
__device__ __nv_bfloat16 g_poolt_l[BATCH * 144 * CHP]; // conv1 out lo
__device__ float g_feat[BATCH * DIN];                  // conv2 output fp32 (router)
__device__ __nv_bfloat16 g_featbf[BATCH * DIN];        // conv2 output bf16 (gemm1)
__device__ __nv_bfloat16 g_w1t[NEXP * DH * DIN];       // W1e transposed bf16 [5][128][3200]
__device__ __nv_bfloat16 g_w2t[NEXP * DH * DH];        // W2e transposed bf16 [5][g][h]
__device__ float g_wgT[10 * DIN];                      // [Wg|Wglu]^T fp32
__device__ float g_gw  [BATCH * NEXP];                 // routing weights [B,5]
__device__ __nv_bfloat16 g_e1bf[BATCH * NEXP * DH];    // expert layer-1 bf16 [B,640]

// =========================== PTX helpers (baseline ISA only) ====================
__device__ __forceinline__ uint32_t smem_u32(const void* p) {
    uint32_t a;
    asm("{ .reg .u64 t; cvta.to.shared.u64 t, %1; cvt.u32.u64 %0, t; }" : "=r"(a) : "l"(p));
    return a;
}
__device__ __forceinline__ void cp_async16(uint32_t dst, const void* src) {
    asm volatile("cp.async.cg.shared.global [%0], [%1], 16;" :: "r"(dst), "l"(src) : "memory");
}
#define CP_COMMIT() asm volatile("cp.async.commit_group;" ::: "memory")
#define CP_WAIT(n)  asm volatile("cp.async.wait_group %0;" :: "n"(n) : "memory")

__device__ __forceinline__ void ldsm_x4(uint32_t addr, uint32_t& r0, uint32_t& r1,
                                        uint32_t& r2, uint32_t& r3) {
    asm volatile("ldmatrix.sync.aligned.m8n8.x4.shared.b16 {%0,%1,%2,%3}, [%4];"
                 : "=r"(r0), "=r"(r1), "=r"(r2), "=r"(r3) : "r"(addr));
}
__device__ __forceinline__ void mma_bf16(float* d, const uint32_t* a, const uint32_t* b) {
    asm volatile("mma.sync.aligned.m16n8k16.row.col.f32.bf16.bf16.f32 "
                 "{%0,%1,%2,%3}, {%4,%5,%6,%7}, {%8,%9}, {%0,%1,%2,%3};"
                 : "+f"(d[0]), "+f"(d[1]), "+f"(d[2]), "+f"(d[3])
                 : "r"(a[0]), "r"(a[1]), "r"(a[2]), "r"(a[3]), "r"(b[0]), "r"(b[1]));
}
__device__ __forceinline__ uint32_t bf16pack(float a, float b) {
    return (uint32_t)__bfloat16_as_ushort(__float2bfloat16(a)) |
           ((uint32_t)__bfloat16_as_ushort(__float2bfloat16(b)) << 16);
}

// ========= Kernel 1: conv1 (5x5) + ReLU + maxpool -> pool_t hi/lo (2 img/CTA) ===
// grid = BATCH/2, block = 288 (two 144-thread halves). Layout [b][pos][CHP].
__global__ void k_conv1pool(const float* __restrict__ x,
                            const float* __restrict__ w,
                            const float* __restrict__ bias,
                            __nv_bfloat16* __restrict__ ph,
                            __nv_bfloat16* __restrict__ pl) {
    __shared__ float s_img[2 * 784];
    __shared__ float s_w[400];
    __shared__ float s_b[16];
    int b0 = blockIdx.x * 2;
    int tid = threadIdx.x;
    for (int i = tid; i < 2 * 784; i += 288)
        s_img[i] = x[(size_t)b0 * 784 + i];
    for (int i = tid; i < 400; i += 288) s_w[i] = w[i];
    if (tid < 16) s_b[tid] = bias[tid];
    __syncthreads();

    int img = tid / 144;
    int t2 = tid - img * 144;
    int py = t2 / 12, px = t2 % 12;
    const float* im = &s_img[img * 784];
    float xr[6][6];
#pragma unroll
    for (int r = 0; r < 6; r++)
#pragma unroll
        for (int c = 0; c < 6; c++)
            xr[r][c] = im[(2 * py + r) * 28 + 2 * px + c];

    float v[16];
#pragma unroll
    for (int ch = 0; ch < 16; ch++) {
        float bb = s_b[ch];
        float a00 = bb, a01 = bb, a10 = bb, a11 = bb;
        const float* wc = &s_w[ch * 25];
#pragma unroll
        for (int ky = 0; ky < 5; ky++)
#pragma unroll
            for (int kx = 0; kx < 5; kx++) {
                float wv = wc[ky * 5 + kx];
                a00 += wv * xr[ky][kx];
                a01 += wv * xr[ky][kx + 1];
                a10 += wv * xr[ky + 1][kx];
                a11 += wv * xr[ky + 1][kx + 1];
            }
        v[ch] = fmaxf(fmaxf(fmaxf(a00, a01), fmaxf(a10, a11)), 0.0f);
    }

    int pbase = ((b0 + img) * 144 + py * 12 + px) * CHP;
#pragma unroll
    for (int ch = 0; ch < 16; ch += 2) {
        __nv_bfloat16 h0 = __float2bfloat16(v[ch]);
        __nv_bfloat16 h1 = __float2bfloat16(v[ch + 1]);
        float h0f = __bfloat162float(h0), h1f = __bfloat162float(h1);
        *(uint32_t*)(ph + pbase + ch) =
            (uint32_t)__bfloat16_as_ushort(h0) | ((uint32_t)__bfloat16_as_ushort(h1) << 16);
        *(uint32_t*)(pl + pbase + ch) = bf16pack(v[ch] - h0f, v[ch + 1] - h1f);
    }
}

// ====== Kernel 2: conv2 via HMMA implicit conv, 3-pass split-bf16 (fp32-exact) ==
#define C2_POOLH 0
#define C2_POOLL 13824
#define C2_BHO   27648
#define C2_BLO   41472
#define C2_OUTF  0
#define C2_BIAS  55296
#define C2_SMEM  55424
__global__ void __launch_bounds__(256)
k_conv2_mma(const __nv_bfloat16* __restrict__ ph,
            const __nv_bfloat16* __restrict__ pl,
            const float* __restrict__ w2,     // [32][16][3][3]
            const float* __restrict__ bias,
            float* __restrict__ feat,
            __nv_bfloat16* __restrict__ featbf) {
    extern __shared__ __align__(16) unsigned char sm[];
    uint32_t sb = smem_u32(sm);
    int tid = threadIdx.x;
    int w8 = tid >> 5, lane = tid & 31;
    int b0 = blockIdx.x * 2;
    int img = w8 >> 2;
    int wbase = (w8 & 3) * 32;

    for (int c = tid; c < 1728; c += 256) {
        int im = c / 864; int r = c % 864; int plane = r / 432; int off = (r % 432) * 16;
        uint32_t dst = sb + (plane ? C2_POOLL : C2_POOLH) + im * 6912 + off;
        const __nv_bfloat16* src = (plane ? pl : ph) + (size_t)(b0 + im) * (144 * CHP);
        cp_async16(dst, (const char*)src + off);
    }
    CP_COMMIT();

    for (int i = tid; i < 4608; i += 256) {
        int tap = i >> 9; int oc = (i >> 4) & 31; int ch = i & 15;
        float v = w2[(oc * 16 + ch) * 9 + tap];
        __nv_bfloat16 h = __float2bfloat16(v);
        int off = ((tap * 32 + oc) * CHP + ch) * 2;
        *(__nv_bfloat16*)(sm + C2_BHO + off) = h;
        *(__nv_bfloat16*)(sm + C2_BLO + off) = __float2bfloat16(v - __bfloat162float(h));
    }
    if (tid < 32) *(float*)(sm + C2_BIAS + tid * 4) = bias[tid];
    CP_WAIT(0);
    __syncthreads();

    int posIdx[2];
#pragma unroll
    for (int mi = 0; mi < 2; mi++) {
        int pos = wbase + mi * 16 + (lane & 15);
        pos = min(pos, 99);
        posIdx[mi] = (pos / 10) * 12 + (pos % 10);
    }
    int chOff = (lane >> 4) * 16;
    uint32_t aBaseH = sb + C2_POOLH + img * 6912 + chOff;
    uint32_t aBaseL = sb + C2_POOLL + img * 6912 + chOff;
    int bRow = (lane & 7) + (lane >> 4) * 8;
    int bKb = ((lane >> 3) & 1) * 16;
    uint32_t bBaseH = sb + C2_BHO + bRow * (CHP * 2) + bKb;
    uint32_t bBaseL = sb + C2_BLO + bRow * (CHP * 2) + bKb;

    float acc[2][4][4];
#pragma unroll
    for (int i = 0; i < 2; i++)
#pragma unroll
        for (int j = 0; j < 4; j++)
#pragma unroll
            for (int q = 0; q < 4; q++) acc[i][j][q] = 0.0f;

    const int tapOff[9] = {0, 1, 2, 12, 13, 14, 24, 25, 26};
#pragma unroll
    for (int tap = 0; tap < 9; tap++) {
        int to = tapOff[tap] * (CHP * 2);
        uint32_t ah[2][4], al[2][4], bh[4][2], bl[4][2];
#pragma unroll
        for (int mi = 0; mi < 2; mi++) {
            ldsm_x4(aBaseH + posIdx[mi] * (CHP * 2) + to, ah[mi][0], ah[mi][1], ah[mi][2], ah[mi][3]);
            ldsm_x4(aBaseL + posIdx[mi] * (CHP * 2) + to, al[mi][0], al[mi][1], al[mi][2], al[mi][3]);
        }
#pragma unroll
        for (int j2 = 0; j2 < 2; j2++) {
            uint32_t off = (tap * 32 + j2 * 16) * (CHP * 2);
            ldsm_x4(bBaseH + off, bh[2 * j2][0], bh[2 * j2][1], bh[2 * j2 + 1][0], bh[2 * j2 + 1][1]);
            ldsm_x4(bBaseL + off, bl[2 * j2][0], bl[2 * j2][1], bl[2 * j2 + 1][0], bl[2 * j2 + 1][1]);
        }
#pragma unroll
        for (int mi = 0; mi < 2; mi++)
#pragma unroll
            for (int nj = 0; nj < 4; nj++) {
                mma_bf16(acc[mi][nj], ah[mi], bh[nj]);
                mma_bf16(acc[mi][nj], ah[mi], bl[nj]);
                mma_bf16(acc[mi][nj], al[mi], bh[nj]);
            }
    }

    __syncthreads();   // all smem reads done — OUTF may overwrite pool/weights

#pragma unroll
    for (int mi = 0; mi < 2; mi++) {
        int pr = wbase + mi * 16 + (lane >> 2);
#pragma unroll
        for (int nj = 0; nj < 4; nj++) {
            int c0 = nj * 8 + (lane & 3) * 2;
            float bb0 = *(float*)(sm + C2_BIAS + c0 * 4);
            float bb1 = *(float*)(sm + C2_BIAS + (c0 + 1) * 4);
            float* o = (float*)(sm + C2_OUTF) + img * 3616;
            if (pr < 100) {
                o[c0 * 113 + pr]       = fmaxf(acc[mi][nj][0] + bb0, 0.0f);
                o[(c0 + 1) * 113 + pr] = fmaxf(acc[mi][nj][1] + bb1, 0.0f);
            }
            if (pr + 8 < 100) {
                o[c0 * 113 + pr + 8]       = fmaxf(acc[mi][nj][2] + bb0, 0.0f);
                o[(c0 + 1) * 113 + pr + 8] = fmaxf(acc[mi][nj][3] + bb1, 0.0f);
            }
        }
    }
    __syncthreads();

    for (int i = tid; i < 3200; i += 256) {
        int im = i / 1600;
        int p2 = i - im * 1600;
        int oc = p2 / 50;
        int pos = (p2 - oc * 50) * 2;
        const float* o = (const float*)(sm + C2_OUTF) + im * 3616 + oc * 113 + pos;
        float v0 = o[0], v1 = o[1];
        size_t g = (size_t)(b0 + im) * DIN + oc * 100 + pos;
        float2 fv = {v0, v1};
        *(float2*)(feat + g) = fv;
        *(uint32_t*)(featbf + g) = bf16pack(v0, v1);
    }
}

// ================ Kernel 2b: W1e [5,3200,128] fp32 -> W1t [5,128,3200] bf16 =====
__global__ void k_w1_convert(const float* __restrict__ W1e,
                             __nv_bfloat16* __restrict__ W1t) {
    __shared__ float t[32][33];
    int e = blockIdx.z;
    int k0 = blockIdx.x * 32;
    int n0 = blockIdx.y * 32;
    int tx = threadIdx.x, ty = threadIdx.y;
    const float* Win = W1e + (size_t)e * DIN * DH;
    __nv_bfloat16* Wout = W1t + (size_t)e * DH * DIN;
#pragma unroll
    for (int yy = ty; yy < 32; yy += 8)
        t[yy][tx] = Win[(size_t)(k0 + yy) * DH + n0 + tx];
    __syncthreads();
#pragma unroll
    for (int yy = ty; yy < 32; yy += 8)
        Wout[(size_t)(n0 + yy) * DIN + k0 + tx] = __float2bfloat16(t[tx][yy]);
}

// ================ Kernel 2b': W2e [5,128,128] fp32 -> W2t [5][g][h] bf16 ========
__global__ void k_w2_convert(const float* __restrict__ W2e,
                             __nv_bfloat16* __restrict__ W2t) {
    __shared__ float t[32][33];
    int e = blockIdx.z;
    int h0 = blockIdx.x * 32;
    int g0 = blockIdx.y * 32;
    int tx = threadIdx.x, ty = threadIdx.y;
    const float* Win = W2e + (size_t)e * DH * DH;
    __nv_bfloat16* Wout = W2t + (size_t)e * DH * DH;
#pragma unroll
    for (int yy = ty; yy < 32; yy += 8)
        t[yy][tx] = Win[(h0 + yy) * DH + g0 + tx];
    __syncthreads();
#pragma unroll
    for (int yy = ty; yy < 32; yy += 8)
        Wout[(g0 + yy) * DH + h0 + tx] = __float2bfloat16(t[tx][yy]);
}

// ================ Kernel 2c: [Wg|Wglu] -> wgT [10][3200] fp32 ===================
__global__ void k_wgt(const float* __restrict__ Wg, const float* __restrict__ Wgl,
                      float* __restrict__ wgT) {
    int i = blockIdx.x * 256 + threadIdx.x;
    if (i >= 10 * DIN) return;
    int e = i / DIN, k = i % DIN;
    wgT[i] = (e < 5) ? Wg[k * 5 + e] : Wgl[k * 5 + (e - 5)];
}

// ================= Kernel 3: GLU router (fp32, coalesced) =======================
__global__ void k_router(const float* __restrict__ feat,
                         const float* __restrict__ wgT,
                         const float* __restrict__ bg, const float* __restrict__ bgl,
                         float* __restrict__ gw) {
    int warp = (blockIdx.x * blockDim.x + threadIdx.x) >> 5;
    int lane = threadIdx.x & 31;
    if (warp >= BATCH) return;
    const float4* f4 = (const float4*)(feat + (size_t)warp * DIN);
    float acc[10];
#pragma unroll
    for (int e = 0; e < 10; e++) acc[e] = 0.0f;
#pragma unroll 5
    for (int it = 0; it < 25; it++) {
        int k4 = it * 32 + lane;
        float4 fv = f4[k4];
#pragma unroll
        for (int e = 0; e < 10; e++) {
            float4 wv = ((const float4*)(wgT + e * DIN))[k4];
            acc[e] += fv.x * wv.x + fv.y * wv.y + fv.z * wv.z + fv.w * wv.w;
        }
    }
#pragma unroll
    for (int off = 16; off; off >>= 1)
#pragma unroll
        for (int e = 0; e < 10; e++)
            acc[e] += __shfl_down_sync(0xFFFFFFFFu, acc[e], off);

    if (lane == 0) {
        float gate[NEXP];
#pragma unroll
        for (int e = 0; e < NEXP; e++) {
            float g = acc[e] + bg[e];
            float s = 1.0f / (1.0f + expf(-(acc[5 + e] + bgl[e])));
            gate[e] = g * s;
        }
        float v0 = -1e30f, v1 = -1e30f, v2 = -1e30f;
        int i0 = 0, i1 = 0, i2 = 0;
#pragma unroll
        for (int e = 0; e < NEXP; e++) {
            float g = gate[e];
            if (g > v0)      { v2 = v1; i2 = i1; v1 = v0; i1 = i0; v0 = g; i0 = e; }
            else if (g > v1) { v2 = v1; i2 = i1; v1 = g;  i1 = e; }
            else if (g > v2) { v2 = g;  i2 = e; }
        }
        float e1 = expf(v1 - v0);
        float e2 = expf(v2 - v0);
        float inv = 1.0f / (1.0f + e1 + e2);
        float wout[NEXP];
#pragma unroll
        for (int e = 0; e < NEXP; e++) wout[e] = 0.0f;
        wout[i0] = inv; wout[i1] = e1 * inv; wout[i2] = e2 * inv;
#pragma unroll
        for (int e = 0; e < NEXP; e++) gw[warp * NEXP + e] = wout[e];
    }
}

// ===== Kernel 4: e1 = tanh(feat @ W1e + b1e) — HMMA, 3-stage cp.async pipeline ==
#define BKC   32
#define NTC   (DIN / BKC)          // 100 k-chunks
#define PITCH 80                   // bytes per 32-bf16 row
#define G1_TILE (128 * PITCH)      // 10240 per operand stage
#define G1_SMEM (6 * G1_TILE)      // 3 stages x (A + B) = 61440
__global__ void __launch_bounds__(256)
k_gemm1_mma(const __nv_bfloat16* __restrict__ A,
            const __nv_bfloat16* __restrict__ Bt,
            const float* __restrict__ b1e,
            __nv_bfloat16* __restrict__ E1bf) {     // [8192,640] bf16
    extern __shared__ __align__(128) unsigned char dsm[];
    uint32_t sA0 = smem_u32(dsm);
    uint32_t sB0 = sA0 + 3 * G1_TILE;

    int tid = threadIdx.x;
    int w = tid >> 5, lane = tid & 31;
    int wm = w & 3, wn = w >> 2;
    int mb = blockIdx.x, e = blockIdx.y;

    const __nv_bfloat16* Ab = A  + (size_t)(mb * 128) * DIN;
    const __nv_bfloat16* Bb = Bt + (size_t)e * DH * DIN;

    float acc[2][8][4];
#pragma unroll
    for (int i = 0; i < 2; i++)
#pragma unroll
        for (int j = 0; j < 8; j++)
#pragma unroll
            for (int q = 0; q < 4; q++) acc[i][j][q] = 0.0f;

    int lr = tid >> 1;
    int lc = (tid & 1) * 2;
    auto load_tile = [&](int t, int s) {
        int k0 = t * BKC;
        uint32_t aD = sA0 + s * G1_TILE + lr * PITCH + lc * 16;
        uint32_t bD = sB0 + s * G1_TILE + lr * PITCH + lc * 16;
        const __nv_bfloat16* aS = Ab + (size_t)lr * DIN + k0 + lc * 8;
        const __nv_bfloat16* bS = Bb + (size_t)lr * DIN + k0 + lc * 8;
        cp_async16(aD,      aS);
        cp_async16(aD + 16, aS + 8);
        cp_async16(bD,      bS);
        cp_async16(bD + 16, bS + 8);
    };

    load_tile(0, 0); CP_COMMIT();
    load_tile(1, 1); CP_COMMIT();

    int aRow = (lane & 7) + ((lane >> 3) & 1) * 8;
    int aKb  = (lane >> 4) * 16;
    int bRow = (lane & 7) + (lane >> 4) * 8;
    int bKb  = ((lane >> 3) & 1) * 16;

    int s = 0;                     // stage = t % 3
    for (int t = 0; t < NTC; t++) {
        CP_WAIT(1);                // tile t's group complete (t+1 may pend)
        __syncthreads();           // everyone done computing t-1 before we refill its buffer
        if (t + 2 < NTC) {
            int s2 = s + 2; if (s2 >= 3) s2 -= 3;
            load_tile(t + 2, s2);
        }
        CP_COMMIT();               // always commit (keeps group accounting uniform)

        uint32_t aT = sA0 + s * G1_TILE;
        uint32_t bT = sB0 + s * G1_TILE;
#pragma unroll
        for (int ks = 0; ks < 2; ks++) {
            uint32_t a[2][4], b[8][2];
#pragma unroll
            for (int i = 0; i < 2; i++) {
                uint32_t addr = aT + (wm * 32 + i * 16 + aRow) * PITCH + ks * 32 + aKb;
                ldsm_x4(addr, a[i][0], a[i][1], a[i][2], a[i][3]);
            }
#pragma unroll
            for (int j2 = 0; j2 < 4; j2++) {
                uint32_t addr = bT + (wn * 64 + j2 * 16 + bRow) * PITCH + ks * 32 + bKb;
                ldsm_x4(addr, b[2 * j2][0], b[2 * j2][1], b[2 * j2 + 1][0], b[2 * j2 + 1][1]);
            }
#pragma unroll
            for (int i = 0; i < 2; i++)
#pragma unroll
                for (int j = 0; j < 8; j++)
                    mma_bf16(acc[i][j], a[i], b[j]);
        }
        if (++s == 3) s = 0;
    }

    const float* bias = b1e + e * DH;
    int qr = lane >> 2;
    int qc = (lane & 3) * 2;
#pragma unroll
    for (int i = 0; i < 2; i++) {
        int m0 = mb * 128 + wm * 32 + i * 16 + qr;
#pragma unroll
        for (int j = 0; j < 8; j++) {
            int c = wn * 64 + j * 8 + qc;
            float b0 = __ldg(&bias[c]);
            float b1 = __ldg(&bias[c + 1]);
            uint32_t p0 = bf16pack(tanhf(acc[i][j][0] + b0), tanhf(acc[i][j][1] + b1));
            uint32_t p1 = bf16pack(tanhf(acc[i][j][2] + b0), tanhf(acc[i][j][3] + b1));
            *(uint32_t*)(E1bf + (size_t)m0 * (NEXP * DH) + e * DH + c) = p0;
            *(uint32_t*)(E1bf + (size_t)(m0 + 8) * (NEXP * DH) + e * DH + c) = p1;
        }
    }
}

// ====== Kernel 5: expert-2 via HMMA bf16 + weighted combine + head + softmax ====
// grid 256 (32 rows/CTA), 256 threads (8 warps; warp w owns output cols [w*16,w*16+16)).
#define E2P   272                       // smem row pitch bytes (136 bf16)
#define E2_SA  0                        // A: 32 x 136 bf16 = 8704
#define E2_SB  8704                     // B: 128 x 136 bf16 = 34816
#define E2_MOE 43520                    // 32 x 128 f32 = 16384
#define E2_WS  59904                    // 1280 f32 = 5120
#define E2_GW  65024                    // 160 f32 = 640
#define E2_LOG 65664                    // 320 f32 = 1280
#define E2_SMEM 66944
__global__ void __launch_bounds__(256)
k_expert2_mma(const __nv_bfloat16* __restrict__ E1bf,   // [8192,640]
              const __nv_bfloat16* __restrict__ W2t,    // [5][g][h]
              const float* __restrict__ b2e,            // [5,128]
              const float* __restrict__ gw,             // [8192,5]
              const float* __restrict__ Ws,             // [128,10]
              const float* __restrict__ bs,             // [10]
              float* __restrict__ out) {                // [8192,10]
    extern __shared__ __align__(16) unsigned char dsm[];
    uint32_t sb = smem_u32(dsm);
    int tid = threadIdx.x;
    int w = tid >> 5, lane = tid & 31;
    int b0 = blockIdx.x * 32;

    float* s_ws  = (float*)(dsm + E2_WS);
    float* s_gw  = (float*)(dsm + E2_GW);
    float* s_moe = (float*)(dsm + E2_MOE);
    float* s_log = (float*)(dsm + E2_LOG);

    for (int i = tid; i < 1280; i += 256) s_ws[i] = Ws[i];
    for (int i = tid; i < 160; i += 256)  s_gw[i] = gw[b0 * NEXP + i];

    int aRow = (lane & 7) + ((lane >> 3) & 1) * 8;
    int aKb  = (lane >> 4) * 16;
    int bRow = (lane & 7) + (lane >> 4) * 8 + w * 16;
    int bKb  = ((lane >> 3) & 1) * 16;

    float moe[2][2][4];
#pragma unroll
    for (int i = 0; i < 2; i++)
#pragma unroll
        for (int j = 0; j < 2; j++)
#pragma unroll
            for (int q = 0; q < 4; q++) moe[i][j][q] = 0.0f;

    for (int e = 0; e < NEXP; e++) {
        __syncthreads();   // prior compute done before overwriting tiles
        // A: 32 rows x 16 chunks = 512; B: 128 rows x 16 chunks = 2048
        for (int c = tid; c < 512; c += 256) {
            int r = c >> 4, ck = c & 15;
            cp_async16(sb + E2_SA + r * E2P + ck * 16,
                       E1bf + (size_t)(b0 + r) * (NEXP * DH) + e * DH + ck * 8);
        }
        for (int c = tid; c < 2048; c += 256) {
            int r = c >> 4, ck = c & 15;
            cp_async16(sb + E2_SB + r * E2P + ck * 16,
                       W2t + (size_t)e * DH * DH + r * DH + ck * 8);
        }
        CP_COMMIT(); CP_WAIT(0);
        __syncthreads();

        float acc[2][2][4];
#pragma unroll
        for (int i = 0; i < 2; i++)
#pragma unroll
            for (int j = 0; j < 2; j++)
#pragma unroll
                for (int q = 0; q < 4; q++) acc[i][j][q] = 0.0f;

#pragma unroll
        for (int k16 = 0; k16 < 8; k16++) {
            uint32_t a[2][4], b[2][2];
#pragma unroll
            for (int i = 0; i < 2; i++)
                ldsm_x4(sb + E2_SA + (i * 16 + aRow) * E2P + k16 * 32 + aKb,
                        a[i][0], a[i][1], a[i][2], a[i][3]);
            ldsm_x4(sb + E2_SB + bRow * E2P + k16 * 32 + bKb,
                    b[0][0], b[0][1], b[1][0], b[1][1]);
#pragma unroll
            for (int i = 0; i < 2; i++)
#pragma unroll
                for (int j = 0; j < 2; j++)
                    mma_bf16(acc[i][j], a[i], b[j]);
        }

        // pre-act + tanh + gw-weighted accumulate
#pragma unroll
        for (int i = 0; i < 2; i++)
#pragma unroll
            for (int j = 0; j < 2; j++)
#pragma unroll
                for (int q = 0; q < 4; q++) {
                    int row = i * 16 + (lane >> 2) + ((q >> 1) ? 8 : 0);
                    int g = w * 16 + j * 8 + (lane & 3) * 2 + (q & 1);
                    float pre = acc[i][j][q] + __ldg(&b2e[e * DH + g]);
                    moe[i][j][q] += s_gw[row * NEXP + e] * tanhf(pre);
                }
    }

    __syncthreads();
#pragma unroll
    for (int i = 0; i < 2; i++)
#pragma unroll
        for (int j = 0; j < 2; j++)
#pragma unroll
            for (int q = 0; q < 4; q++) {
                int row = i * 16 + (lane >> 2) + ((q >> 1) ? 8 : 0);
                int g = w * 16 + j * 8 + (lane & 3) * 2 + (q & 1);
                s_moe[row * DH + g] = moe[i][j][q];
            }
    __syncthreads();

    for (int i = tid; i < 320; i += 256) {
        int r = i / 10, c = i % 10;
        float a = __ldg(&bs[c]);
#pragma unroll 16
        for (int hh = 0; hh < 128; hh++)
            a += s_moe[r * DH + hh] * s_ws[hh * 10 + c];
        s_log[r * 10 + c] = a;
    }
    __syncthreads();
    if (tid < 32) {
        int r = tid;
        float m = -1e30f;
#pragma unroll
        for (int c = 0; c < 10; c++) m = fmaxf(m, s_log[r * 10 + c]);
        float ex[10], ssum = 0.0f;
#pragma unroll
        for (int c = 0; c < 10; c++) { ex[c] = expf(s_log[r * 10 + c] - m); ssum += ex[c]; }
        float inv = 1.0f / ssum;
        float* orow = out + (size_t)(b0 + r) * 10;
#pragma unroll
        for (int c = 0; c < 10; c++) orow[c] = ex[c] * inv;
    }
}

// =============================== launcher =======================================
extern "C" void kernel_launch(void* const* d_in, const int* in_sizes, int n_in,
                              void* d_out, int out_size) {
    const float* x       = (const float*)d_in[0];
    const float* conv1_w = (const float*)d_in[1];
    const float* conv1_b = (const float*)d_in[2];
    const float* conv2_w = (const float*)d_in[3];
    const float* conv2_b = (const float*)d_in[4];
    const float* Wg      = (const float*)d_in[5];
    const float* bg      = (const float*)d_in[6];
    const float* Wglu    = (const float*)d_in[7];
    const float* bglu    = (const float*)d_in[8];
    const float* W1e     = (const float*)d_in[9];
    const float* b1e     = (const float*)d_in[10];
    const float* W2e     = (const float*)d_in[11];
    const float* b2e     = (const float*)d_in[12];
    const float* Ws      = (const float*)d_in[13];
    const float* bs      = (const float*)d_in[14];
    float* out = (float*)d_out;

    float *feat, *wgT, *gwp;
    __nv_bfloat16 *poolh, *pooll, *featbf, *w1t, *w2t, *e1bf;
    cudaGetSymbolAddress((void**)&poolh,  g_poolt_h);
    cudaGetSymbolAddress((void**)&pooll,  g_poolt_l);
    cudaGetSymbolAddress((void**)&feat,   g_feat);
    cudaGetSymbolAddress((void**)&featbf, g_featbf);
    cudaGetSymbolAddress((void**)&w1t,    g_w1t);
    cudaGetSymbolAddress((void**)&w2t,    g_w2t);
    cudaGetSymbolAddress((void**)&wgT,    g_wgT);
    cudaGetSymbolAddress((void**)&gwp,    g_gw);
    cudaGetSymbolAddress((void**)&e1bf,   g_e1bf);

    cudaFuncSetAttribute(k_conv2_mma,   cudaFuncAttributeMaxDynamicSharedMemorySize, C2_SMEM);
    cudaFuncSetAttribute(k_gemm1_mma,   cudaFuncAttributeMaxDynamicSharedMemorySize, G1_SMEM);
    cudaFuncSetAttribute(k_expert2_mma, cudaFuncAttributeMaxDynamicSharedMemorySize, E2_SMEM);

    k_wgt<<<(10 * DIN + 255) / 256, 256>>>(Wg, Wglu, wgT);
    dim3 gW(DIN / 32, DH / 32, NEXP);
    k_w1_convert<<<gW, dim3(32, 8)>>>(W1e, w1t);
    dim3 gW2(DH / 32, DH / 32, NEXP);
    k_w2_convert<<<gW2, dim3(32, 8)>>>(W2e, w2t);
    k_conv1pool<<<BATCH / 2, 288>>>(x, conv1_w, conv1_b, poolh, pooll);
    k_conv2_mma<<<BATCH / 2, 256, C2_SMEM>>>(poolh, pooll, conv2_w, conv2_b, feat, featbf);
    k_router<<<BATCH / 8, 256>>>(feat, wgT, bg, bglu, gwp);
    dim3 g4(BATCH / 128, NEXP);
    k_gemm1_mma<<<g4, 256, G1_SMEM>>>(featbf, w1t, b1e, e1bf);
    k_expert2_mma<<<BATCH / 32, 256, E2_SMEM>>>(e1bf, w2t, b2e, gwp, Ws, bs, out);
}